// round 2
// baseline (speedup 1.0000x reference)
#include <cuda_runtime.h>
#include <cuda_bf16.h>

// SimplePatchScorer: x (512,3,224,224) f32, W (1,768) f32, b (1,) f32
// out (512,196) f32.
//
// Derivation of the scramble:
//   flat index f = ((((b*16+i)*16+j)*3+c)*14+hn)*14+wn
//                = b*(196*768) + t*588 + e,  t = i*16+j, e = c*196+hn*14+wn
//   row r = f/768 (global row = b*196 + (t*588+e)/768), weight col k = f%768.
// For fixed (b,i,j) the 588 elements span a contiguous f-window of width 588
// < 768  ->  at most 2 output rows per thread. Register-accumulate into 2
// accumulators, combine via shared atomics (<=2 per thread), write out once.

#define BATCH   512
#define CIMG    3
#define HW      224
#define PATCH   16
#define NPATCH  14          // 224/16
#define NROWS   196         // 14*14 outputs per image
#define KLEN    768         // 3*16*16
#define IMG_ELEMS (CIMG*HW*HW)   // 150528
#define CH_STRIDE (HW*HW)        // 50176
#define ROW_STRIDE (PATCH*HW)    // 3584

__global__ __launch_bounds__(256, 4)
void patch_scorer_kernel(const float* __restrict__ x,
                         const float* __restrict__ W,
                         const float* __restrict__ bias,
                         float* __restrict__ out)
{
    __shared__ float sW[KLEN];
    __shared__ float sAcc[NROWS];

    const int t = threadIdx.x;          // 0..255  == i*16 + j
    const int b = blockIdx.x;           // image index

    // stage weights + zero accumulators
    sW[t]       = W[t];
    sW[t + 256] = W[t + 256];
    sW[t + 512] = W[t + 512];
    if (t < NROWS) sAcc[t] = 0.0f;
    __syncthreads();

    const int i = t >> 4;
    const int j = t & 15;

    const int base = t * 588;           // f' offset of this thread's window
    const int r0   = base / KLEN;       // first (maybe only) local row
    const int k0   = base - r0 * KLEN;  // starting weight column

    const float* xb = x + (size_t)b * IMG_ELEMS + i * HW + j;

    float acc0 = 0.0f;   // contributions with k0+e < 768  -> row r0
    float acc1 = 0.0f;   // contributions with k0+e >= 768 -> row r0+1

    #pragma unroll
    for (int c = 0; c < CIMG; ++c) {
        const float* pc = xb + c * CH_STRIDE;
        const int    kc = k0 + c * NROWS;           // k0 + c*196
        for (int hn = 0; hn < NPATCH; ++hn) {
            const float* p  = pc + hn * ROW_STRIDE;
            const int    kh = kc + hn * NPATCH;     // + hn*14
            #pragma unroll
            for (int wn = 0; wn < NPATCH; ++wn) {
                // lanes j=0..15 of each half-warp read 16 consecutive floats:
                // two 64B contiguous chunks per warp-load, fully coalesced.
                const float v = __ldg(&p[wn * PATCH]);
                const int   k = kh + wn;
                if (k < KLEN) {
                    acc0 += v * sW[k];
                } else {
                    acc1 += v * sW[k - KLEN];
                }
            }
        }
    }

    atomicAdd(&sAcc[r0], acc0);
    if (k0 + 587 >= KLEN)               // window wraps into the next row
        atomicAdd(&sAcc[r0 + 1], acc1);

    __syncthreads();

    if (t < NROWS)
        out[b * NROWS + t] = sAcc[t] + bias[0];
}

extern "C" void kernel_launch(void* const* d_in, const int* in_sizes, int n_in,
                              void* d_out, int out_size)
{
    const float* x  = (const float*)d_in[0];   // (512,3,224,224)
    const float* W  = (const float*)d_in[1];   // (1,768)
    const float* bv = (const float*)d_in[2];   // (1,)
    float* out = (float*)d_out;                // (512,196)

    patch_scorer_kernel<<<BATCH, 256>>>(x, W, bv, out);
}

// round 3
// speedup vs baseline: 1.0184x; 1.0184x over previous
#include <cuda_runtime.h>
#include <cuda_bf16.h>

// SimplePatchScorer: x (512,3,224,224) f32, W (1,768) f32, b (1,) f32
// out (512,196) f32.
//
// Index algebra: f' = t*588 + e, t = i*16+j, e = c*196+hn*14+wn.
// row r = f'/768, weight col k = f' mod 768.
// Key facts exploited:
//  (1) Δi=4  ->  Δf' = 37632 = 49*768 exactly: k depends only on (i mod 4),
//      rows shift by exactly +49, wrap position identical. One weight load
//      feeds 4 FMAs (rows i, i+4, i+8, i+12).
//  (2) e-window per thread is 147 wide -> crosses at most one row boundary:
//      two-pass loop, register accumulation, <=8 shared atomics per thread.
//  (3) weight smem swizzled idx = k + (k>>5): conflicting lanes differ by
//      k += 96s -> banks differ by 3s (wrap adds +8) -> conflict-free.

#define BATCH   512
#define CIMG    3
#define HW      224
#define PATCH   16
#define NPATCH  14
#define NROWS   196
#define KLEN    768
#define ECHUNK  147          // 588/4 e-values per thread
#define IMG_ELEMS (CIMG*HW*HW)   // 150528
#define CH_STRIDE (HW*HW)        // 50176
#define ROW_STRIDE (PATCH*HW)    // 3584
#define SWSZ    792          // 768 + 768/32 swizzle padding

__global__ __launch_bounds__(256, 4)
void patch_scorer_kernel(const float* __restrict__ x,
                         const float* __restrict__ W,
                         const float* __restrict__ bias,
                         float* __restrict__ out)
{
    __shared__ float sWs[SWSZ];      // swizzled weights: sWs[k + (k>>5)] = W[k]
    __shared__ float sAcc[NROWS];

    const int tid = threadIdx.x;     // 256 threads
    const int b   = blockIdx.x;      // image index

    // stage weights (swizzled) + zero accumulators
    #pragma unroll
    for (int k = tid; k < KLEN; k += 256)
        sWs[k + (k >> 5)] = W[k];
    if (tid < NROWS) sAcc[tid] = 0.0f;
    __syncthreads();

    // thread decomposition: g = e-chunk, im = i mod 4, j = patch column
    const int g  = tid >> 6;         // 0..3
    const int im = (tid >> 4) & 3;   // 0..3
    const int j  = tid & 15;         // 0..15

    const int t0 = im * 16 + j;      // representative t (i = im)
    const int e0 = g * ECHUNK;

    const int f0 = t0 * 588 + e0;
    const int r0 = f0 / KLEN;        // base row for m=0 stream
    int       k  = f0 - r0 * KLEN;   // starting weight column
    const int n1 = (KLEN - k < ECHUNK) ? (KLEN - k) : ECHUNK;  // iters before wrap

    // initial (c, hn, wn) for e0, and streaming address offset
    int c   = e0 / 196;
    int rem = e0 - c * 196;
    int hn  = rem / NPATCH;
    int wn  = rem - hn * NPATCH;
    int off = c * CH_STRIDE + hn * ROW_STRIDE + wn * PATCH;

    const float* px = x + (size_t)b * IMG_ELEMS + j + im * HW;
    // rows i = im, im+4, im+8, im+12  ->  +0, +4*224, +8*224, +12*224 floats

    float a0 = 0.f, a1 = 0.f, a2 = 0.f, a3 = 0.f;

    int n = 0;
    #pragma unroll 2
    for (; n < n1; ++n) {
        const float w = sWs[k + (k >> 5)];
        const float* p = px + off;
        a0 += p[0]        * w;
        a1 += p[4  * HW]  * w;
        a2 += p[8  * HW]  * w;
        a3 += p[12 * HW]  * w;
        ++k;
        off += PATCH;
        if (++wn == NPATCH) { wn = 0; off += ROW_STRIDE - NPATCH * PATCH; }
    }

    atomicAdd(&sAcc[r0       ], a0);
    atomicAdd(&sAcc[r0 +  49 ], a1);
    atomicAdd(&sAcc[r0 +  98 ], a2);
    atomicAdd(&sAcc[r0 + 147 ], a3);

    if (n1 < ECHUNK) {
        k = 0;
        a0 = a1 = a2 = a3 = 0.f;
        #pragma unroll 2
        for (; n < ECHUNK; ++n) {
            const float w = sWs[k + (k >> 5)];
            const float* p = px + off;
            a0 += p[0]        * w;
            a1 += p[4  * HW]  * w;
            a2 += p[8  * HW]  * w;
            a3 += p[12 * HW]  * w;
            ++k;
            off += PATCH;
            if (++wn == NPATCH) { wn = 0; off += ROW_STRIDE - NPATCH * PATCH; }
        }
        atomicAdd(&sAcc[r0 +   1], a0);
        atomicAdd(&sAcc[r0 +  50], a1);
        atomicAdd(&sAcc[r0 +  99], a2);
        atomicAdd(&sAcc[r0 + 148], a3);
    }

    __syncthreads();

    if (tid < NROWS)
        out[b * NROWS + tid] = sAcc[tid] + bias[0];
}

extern "C" void kernel_launch(void* const* d_in, const int* in_sizes, int n_in,
                              void* d_out, int out_size)
{
    const float* x  = (const float*)d_in[0];   // (512,3,224,224)
    const float* W  = (const float*)d_in[1];   // (1,768)
    const float* bv = (const float*)d_in[2];   // (1,)
    float* out = (float*)d_out;                // (512,196)

    patch_scorer_kernel<<<BATCH, 256>>>(x, W, bv, out);
}